// round 9
// baseline (speedup 1.0000x reference)
#include <cuda_runtime.h>
#include <cuda_fp16.h>
#include <cstdint>
#include <cstddef>

// ---------------- problem constants ----------------
#define BB   2
#define TT   2048
#define DD   1024
#define HH   16
#define KH   64          // D / H
#define NPJ  3088        // 3*D + H
#define MMR  4096        // B*T
#define SCALE_V 0.03125f // 1/sqrt(D)
#define SCH  64          // scan chunk
#define SLB  128         // scan lookback (err <= e^-12.8 ~ 2.7e-6)
#define NCH  (TT/SCH)    // 32

// ---------------- scratch (__device__ globals; no allocations) ----------------
__device__ __half g_xh [MMR*DD];
__device__ __half g_xl [MMR*DD];
__device__ __half g_wih[NPJ*DD];
__device__ __half g_wil[NPJ*DD];
__device__ __half g_woh[DD*DD];
__device__ __half g_wol[DD*DD];
__device__ float  g_proj[(size_t)MMR*NPJ]; // (B*T, 3D+H)
__device__ float  g_vbuf[MMR*DD];          // (B,H,T,K) gated v * scale
__device__ float  g_adec[BB*HH*TT];        // (B,H,T) decay multiplier
__device__ float  g_gbuf[MMR*DD];          // (B,T,D) silu(r)*y
__device__ __half g_gh [MMR*DD];
__device__ __half g_gl [MMR*DD];
__device__ float2 g_psum[BB*HH*NCH];       // partial (sum, sumsq) per group-chunk
__device__ float2 g_stats[BB*HH];          // (mean, rstd)

// ---------------- fp32 -> fp16 hi/lo split (float4 vectorized) ----------------
__global__ void cvt_split_kernel(const float4* __restrict__ in,
                                 __half2* __restrict__ hi, __half2* __restrict__ lo, int n4) {
    int i = blockIdx.x * blockDim.x + threadIdx.x;
    if (i >= n4) return;
    float4 v = in[i];
    __half hx = __float2half_rn(v.x), hy = __float2half_rn(v.y);
    __half hz = __float2half_rn(v.z), hw = __float2half_rn(v.w);
    hi[2*i]   = __halves2half2(hx, hy);
    hi[2*i+1] = __halves2half2(hz, hw);
    lo[2*i]   = __halves2half2(__float2half_rn(v.x - __half2float(hx)),
                               __float2half_rn(v.y - __half2float(hy)));
    lo[2*i+1] = __halves2half2(__float2half_rn(v.z - __half2float(hz)),
                               __float2half_rn(v.w - __half2float(hw)));
}

// ---------------- fused split GEMM: C = Ah*Bh^T + (Ah*Bl^T + Al*Bh^T) ----------------
// 128x128 CTA tile, 4 warps of 64x64 (16 LDSM.x4 per 64 HMMA per warp-iter).
// Correction passes first in fp16 acc, then promoted; main Ah*Bh pass in fp32 acc.
#define BM 128
#define BN 128
#define BK 32
#define AST 40                       // padded smem row stride in halves
#define NSTG 4                       // cp.async pipeline depth
#define STGA (BM*AST*2)              // 10240 bytes per A stage
#define STGB (BN*AST*2)              // 10240 bytes per B stage
#define STG  (STGA+STGB)             // 20480 bytes per stage
#define GSMEM (NSTG*STG)             // 81920 bytes dynamic smem

__device__ __forceinline__ void ldsm4(uint32_t& r0, uint32_t& r1, uint32_t& r2, uint32_t& r3,
                                      uint32_t addr) {
    asm volatile("ldmatrix.sync.aligned.m8n8.x4.shared.b16 {%0,%1,%2,%3}, [%4];"
                 : "=r"(r0), "=r"(r1), "=r"(r2), "=r"(r3) : "r"(addr));
}

extern __shared__ char gsm[];

__global__ void __launch_bounds__(128, 2) gemm3_kernel(
    const __half* __restrict__ Ah, const __half* __restrict__ Al,
    const __half* __restrict__ Bh, const __half* __restrict__ Bl,
    float* __restrict__ C, int M, int N, int K)
{
    const uint32_t sbase = (uint32_t)__cvta_generic_to_shared(gsm);

    const int tid  = threadIdx.x;
    const int warp = tid >> 5, lane = tid & 31;
    const int wm = warp & 1, wn = warp >> 1;      // 2 x 2 warp grid, 64x64 tiles
    const int g  = lane >> 2, tg = lane & 3;
    const int bm = blockIdx.y * BM;
    const int bn = blockIdx.x * BN;
    const int KT = K / BK;
    const int total = 3 * KT;
    const int lr = tid >> 2;          // 0..31
    const int lc = (tid & 3) * 8;     // 0,8,16,24 halves

    // per-thread cp.async targets: 4 A rows + 4 B rows (32-row strides)
    uint32_t dAo[4], dBo[4];
    size_t aof[4], bof[4];
    int pz[4];
#pragma unroll
    for (int r = 0; r < 4; ++r) {
        int row = lr + r * 32;
        dAo[r] = (row * AST + lc) * 2;
        dBo[r] = STGA + (row * AST + lc) * 2;
        aof[r] = (size_t)(bm + row) * K + lc;
        int n = bn + row;
        pz[r]  = (n < N) ? 16 : 0;
        bof[r] = (size_t)((n < N) ? n : N - 1) * K + lc;
    }

    // pass order: 0:(Ah,Bl)  1:(Al,Bh)  [fp16 acc]   2:(Ah,Bh) [fp32 acc]
    auto ISSUE = [&](int chunk) {
        int pair = chunk / KT;
        int kk = (chunk - pair * KT) * BK;
        const __half* Ap = (pair == 1) ? Al : Ah;
        const __half* Bp = (pair == 0) ? Bl : Bh;
        uint32_t st = sbase + (chunk & (NSTG - 1)) * STG;
#pragma unroll
        for (int r = 0; r < 4; ++r) {
            asm volatile("cp.async.cg.shared.global [%0], [%1], 16;\n"
                         :: "r"(st + dAo[r]), "l"(Ap + aof[r] + kk));
            asm volatile("cp.async.cg.shared.global [%0], [%1], 16, %2;\n"
                         :: "r"(st + dBo[r]), "l"(Bp + bof[r] + kk), "r"(pz[r]));
        }
        asm volatile("cp.async.commit_group;\n");
    };

    // ldmatrix per-lane address components
    const uint32_t a_row = wm * 64 + (lane & 15);
    const uint32_t a_ko  = (lane >> 4) << 3;
    const uint32_t b_row = wn * 64 + (lane & 7) + ((lane & 16) >> 1);
    const uint32_t b_ko  = (lane & 8);

    ISSUE(0); ISSUE(1); ISSUE(2);

    // ---- phase A: correction passes, fp16 accumulators (64 regs) ----
    uint32_t acc16[4][8][2];
#pragma unroll
    for (int i = 0; i < 4; i++)
#pragma unroll
        for (int j = 0; j < 8; j++) { acc16[i][j][0] = 0u; acc16[i][j][1] = 0u; }

    for (int it = 0; it < 2 * KT; ++it) {
        asm volatile("cp.async.wait_group 2;\n" ::: "memory");
        __syncthreads();
        if (it + 3 < total) ISSUE(it + 3);

        const uint32_t st = sbase + (it & (NSTG - 1)) * STG;
        const uint32_t Ab = st;
        const uint32_t Bb = st + STGA;
#pragma unroll
        for (int ks = 0; ks < 2; ++ks) {
            uint32_t ra[4][4];
#pragma unroll
            for (int mi = 0; mi < 4; ++mi) {
                uint32_t addr = Ab + ((a_row + mi * 16) * AST + ks * 16 + a_ko) * 2;
                ldsm4(ra[mi][0], ra[mi][1], ra[mi][2], ra[mi][3], addr);
            }
            uint32_t rb[8][2];
#pragma unroll
            for (int ni2 = 0; ni2 < 4; ++ni2) {
                uint32_t addr = Bb + ((b_row + ni2 * 16) * AST + ks * 16 + b_ko) * 2;
                ldsm4(rb[2*ni2][0], rb[2*ni2][1], rb[2*ni2+1][0], rb[2*ni2+1][1], addr);
            }
#pragma unroll
            for (int mi = 0; mi < 4; ++mi)
#pragma unroll
                for (int ni = 0; ni < 8; ++ni)
                    asm volatile(
                        "mma.sync.aligned.m16n8k16.row.col.f16.f16.f16.f16 "
                        "{%0,%1},{%2,%3,%4,%5},{%6,%7},{%0,%1};\n"
                        : "+r"(acc16[mi][ni][0]), "+r"(acc16[mi][ni][1])
                        : "r"(ra[mi][0]), "r"(ra[mi][1]), "r"(ra[mi][2]), "r"(ra[mi][3]),
                          "r"(rb[ni][0]), "r"(rb[ni][1]));
        }
    }

    // ---- promote fp16 corrections into fp32 accumulators ----
    float acc[4][8][4];
#pragma unroll
    for (int mi = 0; mi < 4; ++mi)
#pragma unroll
        for (int ni = 0; ni < 8; ++ni) {
            float2 lo2 = __half22float2(*(const __half2*)&acc16[mi][ni][0]);
            float2 hi2 = __half22float2(*(const __half2*)&acc16[mi][ni][1]);
            acc[mi][ni][0] = lo2.x; acc[mi][ni][1] = lo2.y;
            acc[mi][ni][2] = hi2.x; acc[mi][ni][3] = hi2.y;
        }

    // ---- phase B: main Ah*Bh pass, fp32 accumulators (128 regs) ----
    for (int it = 2 * KT; it < total; ++it) {
        const int rem = total - 1 - it;
        if (rem >= 2)      asm volatile("cp.async.wait_group 2;\n" ::: "memory");
        else if (rem == 1) asm volatile("cp.async.wait_group 1;\n" ::: "memory");
        else               asm volatile("cp.async.wait_group 0;\n" ::: "memory");
        __syncthreads();
        if (it + 3 < total) ISSUE(it + 3);

        const uint32_t st = sbase + (it & (NSTG - 1)) * STG;
        const uint32_t Ab = st;
        const uint32_t Bb = st + STGA;
#pragma unroll
        for (int ks = 0; ks < 2; ++ks) {
            uint32_t ra[4][4];
#pragma unroll
            for (int mi = 0; mi < 4; ++mi) {
                uint32_t addr = Ab + ((a_row + mi * 16) * AST + ks * 16 + a_ko) * 2;
                ldsm4(ra[mi][0], ra[mi][1], ra[mi][2], ra[mi][3], addr);
            }
            uint32_t rb[8][2];
#pragma unroll
            for (int ni2 = 0; ni2 < 4; ++ni2) {
                uint32_t addr = Bb + ((b_row + ni2 * 16) * AST + ks * 16 + b_ko) * 2;
                ldsm4(rb[2*ni2][0], rb[2*ni2][1], rb[2*ni2+1][0], rb[2*ni2+1][1], addr);
            }
#pragma unroll
            for (int mi = 0; mi < 4; ++mi)
#pragma unroll
                for (int ni = 0; ni < 8; ++ni)
                    asm volatile(
                        "mma.sync.aligned.m16n8k16.row.col.f32.f16.f16.f32 "
                        "{%0,%1,%2,%3},{%4,%5,%6,%7},{%8,%9},{%0,%1,%2,%3};\n"
                        : "+f"(acc[mi][ni][0]), "+f"(acc[mi][ni][1]),
                          "+f"(acc[mi][ni][2]), "+f"(acc[mi][ni][3])
                        : "r"(ra[mi][0]), "r"(ra[mi][1]), "r"(ra[mi][2]), "r"(ra[mi][3]),
                          "r"(rb[ni][0]), "r"(rb[ni][1]));
        }
    }

#pragma unroll
    for (int mi = 0; mi < 4; ++mi) {
        int r0 = bm + wm * 64 + mi * 16 + g;
#pragma unroll
        for (int ni = 0; ni < 8; ++ni) {
            int c0 = bn + wn * 64 + ni * 8 + tg * 2;
            if (c0 < N) {
                *(float2*)(C + (size_t)r0       * N + c0) = make_float2(acc[mi][ni][0], acc[mi][ni][1]);
                *(float2*)(C + (size_t)(r0 + 8) * N + c0) = make_float2(acc[mi][ni][2], acc[mi][ni][3]);
            }
        }
    }
}

// ---------------- gate: shifted depthwise conv + silu gating + repack (x4) ----------------
// k_out[b,t,d] = conv_b[d] + sum_{j=0..3} conv_w[d,j] * k[b, t-6+j, d]   (zero-pad t<0)
__global__ void gate_kernel(const float* __restrict__ conv_w, const float* __restrict__ conv_b) {
    int i4 = blockIdx.x * blockDim.x + threadIdx.x;
    if (i4 >= MMR * DD / 4) return;
    int idx = i4 * 4;
    int d  = idx & (DD - 1);
    int bt = idx >> 10;
    int t  = bt & (TT - 1);
    int b  = bt >> 11;

    float4 cw[4];
#pragma unroll
    for (int u = 0; u < 4; ++u) cw[u] = *(const float4*)(conv_w + (d + u) * 4);
    float4 cb = *(const float4*)(conv_b + d);
    float ko[4] = {cb.x, cb.y, cb.z, cb.w};

#pragma unroll
    for (int j = 0; j < 4; ++j) {
        int tt = t - 6 + j;
        if (tt >= 0) {
            float4 kv = *(const float4*)(g_proj + (size_t)(b * TT + tt) * NPJ + 2 * DD + d);
            ko[0] = fmaf(((const float*)&cw[0])[j], kv.x, ko[0]);
            ko[1] = fmaf(((const float*)&cw[1])[j], kv.y, ko[1]);
            ko[2] = fmaf(((const float*)&cw[2])[j], kv.z, ko[2]);
            ko[3] = fmaf(((const float*)&cw[3])[j], kv.w, ko[3]);
        }
    }
    float4 v4 = *(const float4*)(g_proj + (size_t)bt * NPJ + DD + d);
    float ov[4];
    const float* vv = (const float*)&v4;
#pragma unroll
    for (int u = 0; u < 4; ++u) {
        float sk = ko[u] / (1.f + __expf(-ko[u]));
        ov[u] = vv[u] * sk * SCALE_V;
    }
    int h = d >> 6, kk = d & 63;
    *(float4*)(g_vbuf + ((size_t)(b * HH + h) * TT + t) * KH + kk) =
        make_float4(ov[0], ov[1], ov[2], ov[3]);
}

// ---------------- decay multiplier per (b,h,t) ----------------
__global__ void decay_kernel(const float* __restrict__ dp) {
    int idx = blockIdx.x * blockDim.x + threadIdx.x;
    if (idx >= BB * TT * HH) return;
    int h  = idx & (HH - 1);
    int bt = idx >> 4;
    float wv = g_proj[(size_t)bt * NPJ + 3 * DD + h];
    float gg = 1.f / (1.f + expf(-(dp[h] + wv)));
    float a  = expf(-8.f * (1.f - gg) - 0.1f);           // exp(log_decay), <= exp(-0.1)
    int b = bt >> 11, t = bt & (TT - 1);
    g_adec[(b * HH + h) * TT + t] = a;
}

// ---------------- chunked scan, 4-way unrolled, fused silu(r)*y + GN partials ----------------
__global__ void scan_kernel() {
    const int c  = blockIdx.x & (NCH - 1);
    const int bh = blockIdx.x >> 5;
    const int b  = bh >> 4, h = bh & (HH - 1);
    const int k  = threadIdx.x;                          // 0..63
    const int t0 = c * SCH;
    int s0 = t0 - SLB; if (s0 < 0) s0 = 0;
    const float* vp = g_vbuf + (size_t)bh * TT * KH;
    const float* ap = g_adec + (size_t)bh * TT;
    const int col = h * KH + k;

    float y = 0.f;
    for (int s = s0; s < t0; s += 4) {                   // lookback warm-up
        float4 a4 = *(const float4*)(ap + s);
        float v0 = vp[(size_t)(s + 0) * KH + k];
        float v1 = vp[(size_t)(s + 1) * KH + k];
        float v2 = vp[(size_t)(s + 2) * KH + k];
        float v3 = vp[(size_t)(s + 3) * KH + k];
        y = fmaf(a4.x, y, v0);
        y = fmaf(a4.y, y, v1);
        y = fmaf(a4.z, y, v2);
        y = fmaf(a4.w, y, v3);
    }

    float s1 = 0.f, s2 = 0.f;
    for (int sm = t0; sm < t0 + SCH; sm += 4) {
        float4 a4 = *(const float4*)(ap + sm);
        float aa[4] = {a4.x, a4.y, a4.z, a4.w};
        float vv[4], rr[4];
#pragma unroll
        for (int j = 0; j < 4; ++j) {
            vv[j] = vp[(size_t)(sm + j) * KH + k];
            rr[j] = g_proj[(size_t)(b * TT + sm + j) * NPJ + col];
        }
#pragma unroll
        for (int j = 0; j < 4; ++j) {
            y = fmaf(aa[j], y, vv[j]);
            float r  = rr[j];
            float sr = r / (1.f + __expf(-r));
            float gv = sr * y;
            g_gbuf[(size_t)(b * TT + sm + j) * DD + col] = gv;
            s1 += gv;
            s2 = fmaf(gv, gv, s2);
        }
    }

    __shared__ float rs1[64], rs2[64];
    rs1[k] = s1; rs2[k] = s2;
    __syncthreads();
    for (int off = 32; off > 0; off >>= 1) {
        if (k < off) { rs1[k] += rs1[k + off]; rs2[k] += rs2[k + off]; }
        __syncthreads();
    }
    if (k == 0) g_psum[bh * NCH + c] = make_float2(rs1[0], rs2[0]);
}

// ---------------- GroupNorm statistics (deterministic combine) ----------------
__global__ void stats_kernel() {
    int gi = threadIdx.x;
    if (gi >= BB * HH) return;
    float s1 = 0.f, s2 = 0.f;
    for (int c = 0; c < NCH; ++c) {
        float2 p = g_psum[gi * NCH + c];
        s1 += p.x; s2 += p.y;
    }
    const float inv = 1.f / (float)(KH * TT);
    float mean = s1 * inv;
    float var  = s2 * inv - mean * mean;
    g_stats[gi] = make_float2(mean, rsqrtf(var + 1e-5f));
}

// ---------------- normalize + affine + fp16 hi/lo split (x4) ----------------
__global__ void normcvt_kernel(const float* __restrict__ gn_w, const float* __restrict__ gn_b) {
    int i4 = blockIdx.x * blockDim.x + threadIdx.x;
    if (i4 >= MMR * DD / 4) return;
    int idx = i4 * 4;
    int d  = idx & (DD - 1);
    int bt = idx >> 10;
    int b  = bt >> 11;
    int h  = d >> 6;
    float2 st = g_stats[b * HH + h];
    float4 gv = *(const float4*)(g_gbuf + idx);
    float4 w4 = *(const float4*)(gn_w + d);
    float4 b4 = *(const float4*)(gn_b + d);
    float vals[4];
    vals[0] = fmaf((gv.x - st.x) * st.y, w4.x, b4.x);
    vals[1] = fmaf((gv.y - st.x) * st.y, w4.y, b4.y);
    vals[2] = fmaf((gv.z - st.x) * st.y, w4.z, b4.z);
    vals[3] = fmaf((gv.w - st.x) * st.y, w4.w, b4.w);
    __half hh[4], ll[4];
#pragma unroll
    for (int u = 0; u < 4; ++u) {
        hh[u] = __float2half_rn(vals[u]);
        ll[u] = __float2half_rn(vals[u] - __half2float(hh[u]));
    }
    __half2* ph = (__half2*)(g_gh + idx);
    __half2* pl = (__half2*)(g_gl + idx);
    ph[0] = __halves2half2(hh[0], hh[1]);
    ph[1] = __halves2half2(hh[2], hh[3]);
    pl[0] = __halves2half2(ll[0], ll[1]);
    pl[1] = __halves2half2(ll[2], ll[3]);
}

// ---------------- launch ----------------
extern "C" void kernel_launch(void* const* d_in, const int* in_sizes, int n_in,
                              void* d_out, int out_size) {
    const float* x      = (const float*)d_in[0];
    const float* W_in   = (const float*)d_in[1];
    const float* conv_w = (const float*)d_in[2];
    const float* conv_b = (const float*)d_in[3];
    const float* dp     = (const float*)d_in[4];
    const float* gn_w   = (const float*)d_in[5];
    const float* gn_b   = (const float*)d_in[6];
    const float* W_out  = (const float*)d_in[7];
    float* out = (float*)d_out;
    (void)in_sizes; (void)n_in; (void)out_size;

    void *pxh, *pxl, *pwih, *pwil, *pwoh, *pwol, *pproj, *pgh, *pgl;
    cudaGetSymbolAddress(&pxh,  g_xh);
    cudaGetSymbolAddress(&pxl,  g_xl);
    cudaGetSymbolAddress(&pwih, g_wih);
    cudaGetSymbolAddress(&pwil, g_wil);
    cudaGetSymbolAddress(&pwoh, g_woh);
    cudaGetSymbolAddress(&pwol, g_wol);
    cudaGetSymbolAddress(&pproj, g_proj);
    cudaGetSymbolAddress(&pgh,  g_gh);
    cudaGetSymbolAddress(&pgl,  g_gl);

    cudaFuncSetAttribute(gemm3_kernel,
                         cudaFuncAttributeMaxDynamicSharedMemorySize, GSMEM);

    const int TPB = 256;
    cvt_split_kernel<<<(MMR*DD/4 + TPB-1)/TPB, TPB>>>((const float4*)x,
        (__half2*)pxh, (__half2*)pxl, MMR*DD/4);
    cvt_split_kernel<<<(NPJ*DD/4 + TPB-1)/TPB, TPB>>>((const float4*)W_in,
        (__half2*)pwih, (__half2*)pwil, NPJ*DD/4);
    cvt_split_kernel<<<(DD*DD/4 + TPB-1)/TPB, TPB>>>((const float4*)W_out,
        (__half2*)pwoh, (__half2*)pwol, DD*DD/4);

    // GEMM1: proj = x @ W_in^T (split: f16-acc corrections then f32-acc main)
    dim3 gg1((NPJ + BN - 1)/BN, MMR/BM);
    gemm3_kernel<<<gg1, 128, GSMEM>>>((__half*)pxh, (__half*)pxl,
                                      (__half*)pwih, (__half*)pwil,
                                      (float*)pproj, MMR, NPJ, DD);

    gate_kernel <<<(MMR*DD/4 + TPB-1)/TPB, TPB>>>(conv_w, conv_b);
    decay_kernel<<<(BB*TT*HH + TPB-1)/TPB, TPB>>>(dp);
    scan_kernel <<<BB*HH*NCH, 64>>>();
    stats_kernel<<<1, 32>>>();
    normcvt_kernel<<<(MMR*DD/4 + TPB-1)/TPB, TPB>>>(gn_w, gn_b);

    // GEMM2: out = g_norm @ W_out^T
    dim3 gg2(DD/BN, MMR/BM);
    gemm3_kernel<<<gg2, 128, GSMEM>>>((__half*)pgh, (__half*)pgl,
                                      (__half*)pwoh, (__half*)pwol,
                                      out, MMR, DD, DD);
}

// round 10
// speedup vs baseline: 2.1782x; 2.1782x over previous
#include <cuda_runtime.h>
#include <cuda_fp16.h>
#include <cstdint>
#include <cstddef>

// ---------------- problem constants ----------------
#define BB   2
#define TT   2048
#define DD   1024
#define HH   16
#define KH   64          // D / H
#define NPJ  3088        // 3*D + H
#define MMR  4096        // B*T
#define SCALE_V 0.03125f // 1/sqrt(D)
#define SCH  64          // scan chunk
#define SLB  128         // scan lookback (err <= e^-12.8 ~ 2.7e-6)
#define NCH  (TT/SCH)    // 32

// ---------------- scratch (__device__ globals; no allocations) ----------------
__device__ __half g_xh [MMR*DD];
__device__ __half g_wih[NPJ*DD];
__device__ __half g_woh[DD*DD];
__device__ float  g_proj[(size_t)MMR*NPJ]; // (B*T, 3D+H)
__device__ float  g_vbuf[MMR*DD];          // (B,H,T,K) gated v * scale
__device__ float  g_adec[BB*HH*TT];        // (B,H,T) decay multiplier
__device__ float  g_gbuf[MMR*DD];          // (B,T,D) silu(r)*y
__device__ __half g_gh [MMR*DD];
__device__ float2 g_psum[BB*HH*NCH];       // partial (sum, sumsq) per group-chunk
__device__ float2 g_stats[BB*HH];          // (mean, rstd)

// ---------------- fp32 -> fp16 (float4 vectorized) ----------------
__global__ void cvt_kernel(const float4* __restrict__ in, __half2* __restrict__ hi, int n4) {
    int i = blockIdx.x * blockDim.x + threadIdx.x;
    if (i >= n4) return;
    float4 v = in[i];
    hi[2*i]   = __halves2half2(__float2half_rn(v.x), __float2half_rn(v.y));
    hi[2*i+1] = __halves2half2(__float2half_rn(v.z), __float2half_rn(v.w));
}

// ---------------- single-pass fp16 GEMM: C = A*B^T (fp32 accum) ----------------
// R7-proven config: 128x128 CTA tile, 256 threads, 4x2 warps of 32x64.
#define BM 128
#define BN 128
#define BK 32
#define AST 40                       // padded smem row stride in halves
#define NSTG 4                       // cp.async pipeline depth
#define STGA (BM*AST*2)              // 10240 bytes per A stage
#define STGB (BN*AST*2)              // 10240 bytes per B stage
#define STG  (STGA+STGB)             // 20480 bytes per stage
#define GSMEM (NSTG*STG)             // 81920 bytes dynamic smem

__device__ __forceinline__ void ldsm4(uint32_t& r0, uint32_t& r1, uint32_t& r2, uint32_t& r3,
                                      uint32_t addr) {
    asm volatile("ldmatrix.sync.aligned.m8n8.x4.shared.b16 {%0,%1,%2,%3}, [%4];"
                 : "=r"(r0), "=r"(r1), "=r"(r2), "=r"(r3) : "r"(addr));
}

extern __shared__ char gsm[];

__global__ void __launch_bounds__(256, 2) gemm1p_kernel(
    const __half* __restrict__ A, const __half* __restrict__ B,
    float* __restrict__ C, int M, int N, int K)
{
    const uint32_t sbase = (uint32_t)__cvta_generic_to_shared(gsm);

    const int tid  = threadIdx.x;
    const int warp = tid >> 5, lane = tid & 31;
    const int wm = warp & 3, wn = warp >> 2;      // 4 x 2 warp grid
    const int g  = lane >> 2, tg = lane & 3;
    const int bm = blockIdx.y * BM;
    const int bn = blockIdx.x * BN;
    const int KT = K / BK;                        // total k-chunks (single pass)
    const int lr = tid >> 2;          // 0..63
    const int lc = (tid & 3) * 8;     // 0,8,16,24 halves

    const uint32_t dA0 = (lr * AST + lc) * 2;
    const uint32_t dA1 = ((lr + 64) * AST + lc) * 2;

    const int n0 = bn + lr, n1 = bn + lr + 64;
    const int p0 = (n0 < N) ? 16 : 0;
    const int p1 = (n1 < N) ? 16 : 0;
    const size_t aoff0 = (size_t)(bm + lr) * K + lc;
    const size_t aoff1 = (size_t)(bm + lr + 64) * K + lc;
    const size_t boff0 = (size_t)((n0 < N) ? n0 : N - 1) * K + lc;
    const size_t boff1 = (size_t)((n1 < N) ? n1 : N - 1) * K + lc;

    auto ISSUE = [&](int chunk) {
        int kk = chunk * BK;
        uint32_t st = sbase + (chunk & (NSTG - 1)) * STG;
        asm volatile("cp.async.cg.shared.global [%0], [%1], 16;\n"
                     :: "r"(st + dA0), "l"(A + aoff0 + kk));
        asm volatile("cp.async.cg.shared.global [%0], [%1], 16;\n"
                     :: "r"(st + dA1), "l"(A + aoff1 + kk));
        asm volatile("cp.async.cg.shared.global [%0], [%1], 16, %2;\n"
                     :: "r"(st + STGA + dA0), "l"(B + boff0 + kk), "r"(p0));
        asm volatile("cp.async.cg.shared.global [%0], [%1], 16, %2;\n"
                     :: "r"(st + STGA + dA1), "l"(B + boff1 + kk), "r"(p1));
        asm volatile("cp.async.commit_group;\n");
    };

    float acc[2][8][4];
#pragma unroll
    for (int i = 0; i < 2; i++)
#pragma unroll
        for (int j = 0; j < 8; j++)
#pragma unroll
            for (int q = 0; q < 4; q++) acc[i][j][q] = 0.f;

    // ldmatrix per-lane address components
    const uint32_t a_row = wm * 32 + (lane & 15);
    const uint32_t a_ko  = (lane >> 4) << 3;
    const uint32_t b_row = wn * 64 + (lane & 7) + ((lane & 16) >> 1);
    const uint32_t b_ko  = (lane & 8);

    ISSUE(0); ISSUE(1); ISSUE(2);

    for (int it = 0; it < KT; ++it) {
        const int rem = KT - 1 - it;
        if (rem >= 2)      asm volatile("cp.async.wait_group 2;\n" ::: "memory");
        else if (rem == 1) asm volatile("cp.async.wait_group 1;\n" ::: "memory");
        else               asm volatile("cp.async.wait_group 0;\n" ::: "memory");
        __syncthreads();
        if (it + 3 < KT) ISSUE(it + 3);

        const uint32_t st = sbase + (it & (NSTG - 1)) * STG;
        const uint32_t Ab = st;
        const uint32_t Bb = st + STGA;
#pragma unroll
        for (int ks = 0; ks < 2; ++ks) {
            uint32_t ra[2][4];
#pragma unroll
            for (int mi = 0; mi < 2; ++mi) {
                uint32_t addr = Ab + ((a_row + mi * 16) * AST + ks * 16 + a_ko) * 2;
                ldsm4(ra[mi][0], ra[mi][1], ra[mi][2], ra[mi][3], addr);
            }
            uint32_t rb[8][2];
#pragma unroll
            for (int ni2 = 0; ni2 < 4; ++ni2) {
                uint32_t addr = Bb + ((b_row + ni2 * 16) * AST + ks * 16 + b_ko) * 2;
                ldsm4(rb[2*ni2][0], rb[2*ni2][1], rb[2*ni2+1][0], rb[2*ni2+1][1], addr);
            }
#pragma unroll
            for (int mi = 0; mi < 2; ++mi)
#pragma unroll
                for (int ni = 0; ni < 8; ++ni)
                    asm volatile(
                        "mma.sync.aligned.m16n8k16.row.col.f32.f16.f16.f32 "
                        "{%0,%1,%2,%3},{%4,%5,%6,%7},{%8,%9},{%0,%1,%2,%3};\n"
                        : "+f"(acc[mi][ni][0]), "+f"(acc[mi][ni][1]),
                          "+f"(acc[mi][ni][2]), "+f"(acc[mi][ni][3])
                        : "r"(ra[mi][0]), "r"(ra[mi][1]), "r"(ra[mi][2]), "r"(ra[mi][3]),
                          "r"(rb[ni][0]), "r"(rb[ni][1]));
        }
    }

#pragma unroll
    for (int mi = 0; mi < 2; ++mi) {
        int r0 = bm + wm * 32 + mi * 16 + g;
#pragma unroll
        for (int ni = 0; ni < 8; ++ni) {
            int c0 = bn + wn * 64 + ni * 8 + tg * 2;
            if (c0 < N) {
                *(float2*)(C + (size_t)r0       * N + c0) = make_float2(acc[mi][ni][0], acc[mi][ni][1]);
                *(float2*)(C + (size_t)(r0 + 8) * N + c0) = make_float2(acc[mi][ni][2], acc[mi][ni][3]);
            }
        }
    }
}

// ---------------- gate: shifted depthwise conv + silu gating + repack (x4) ----------------
// k_out[b,t,d] = conv_b[d] + sum_{j=0..3} conv_w[d,j] * k[b, t-6+j, d]   (zero-pad t<0)
__global__ void gate_kernel(const float* __restrict__ conv_w, const float* __restrict__ conv_b) {
    int i4 = blockIdx.x * blockDim.x + threadIdx.x;
    if (i4 >= MMR * DD / 4) return;
    int idx = i4 * 4;
    int d  = idx & (DD - 1);
    int bt = idx >> 10;
    int t  = bt & (TT - 1);
    int b  = bt >> 11;

    float4 cw[4];
#pragma unroll
    for (int u = 0; u < 4; ++u) cw[u] = *(const float4*)(conv_w + (d + u) * 4);
    float4 cb = *(const float4*)(conv_b + d);
    float ko[4] = {cb.x, cb.y, cb.z, cb.w};

#pragma unroll
    for (int j = 0; j < 4; ++j) {
        int tt = t - 6 + j;
        if (tt >= 0) {
            float4 kv = *(const float4*)(g_proj + (size_t)(b * TT + tt) * NPJ + 2 * DD + d);
            ko[0] = fmaf(((const float*)&cw[0])[j], kv.x, ko[0]);
            ko[1] = fmaf(((const float*)&cw[1])[j], kv.y, ko[1]);
            ko[2] = fmaf(((const float*)&cw[2])[j], kv.z, ko[2]);
            ko[3] = fmaf(((const float*)&cw[3])[j], kv.w, ko[3]);
        }
    }
    float4 v4 = *(const float4*)(g_proj + (size_t)bt * NPJ + DD + d);
    float ov[4];
    const float* vv = (const float*)&v4;
#pragma unroll
    for (int u = 0; u < 4; ++u) {
        float sk = ko[u] / (1.f + __expf(-ko[u]));
        ov[u] = vv[u] * sk * SCALE_V;
    }
    int h = d >> 6, kk = d & 63;
    *(float4*)(g_vbuf + ((size_t)(b * HH + h) * TT + t) * KH + kk) =
        make_float4(ov[0], ov[1], ov[2], ov[3]);
}

// ---------------- decay multiplier per (b,h,t) ----------------
__global__ void decay_kernel(const float* __restrict__ dp) {
    int idx = blockIdx.x * blockDim.x + threadIdx.x;
    if (idx >= BB * TT * HH) return;
    int h  = idx & (HH - 1);
    int bt = idx >> 4;
    float wv = g_proj[(size_t)bt * NPJ + 3 * DD + h];
    float gg = 1.f / (1.f + expf(-(dp[h] + wv)));
    float a  = expf(-8.f * (1.f - gg) - 0.1f);           // exp(log_decay), <= exp(-0.1)
    int b = bt >> 11, t = bt & (TT - 1);
    g_adec[(b * HH + h) * TT + t] = a;
}

// ---------------- chunked scan, 4-way unrolled, fused silu(r)*y + GN partials ----------------
__global__ void scan_kernel() {
    const int c  = blockIdx.x & (NCH - 1);
    const int bh = blockIdx.x >> 5;
    const int b  = bh >> 4, h = bh & (HH - 1);
    const int k  = threadIdx.x;                          // 0..63
    const int t0 = c * SCH;
    int s0 = t0 - SLB; if (s0 < 0) s0 = 0;
    const float* vp = g_vbuf + (size_t)bh * TT * KH;
    const float* ap = g_adec + (size_t)bh * TT;
    const int col = h * KH + k;

    float y = 0.f;
    for (int s = s0; s < t0; s += 4) {                   // lookback warm-up
        float4 a4 = *(const float4*)(ap + s);
        float v0 = vp[(size_t)(s + 0) * KH + k];
        float v1 = vp[(size_t)(s + 1) * KH + k];
        float v2 = vp[(size_t)(s + 2) * KH + k];
        float v3 = vp[(size_t)(s + 3) * KH + k];
        y = fmaf(a4.x, y, v0);
        y = fmaf(a4.y, y, v1);
        y = fmaf(a4.z, y, v2);
        y = fmaf(a4.w, y, v3);
    }

    float s1 = 0.f, s2 = 0.f;
    for (int sm = t0; sm < t0 + SCH; sm += 4) {
        float4 a4 = *(const float4*)(ap + sm);
        float aa[4] = {a4.x, a4.y, a4.z, a4.w};
        float vv[4], rr[4];
#pragma unroll
        for (int j = 0; j < 4; ++j) {
            vv[j] = vp[(size_t)(sm + j) * KH + k];
            rr[j] = g_proj[(size_t)(b * TT + sm + j) * NPJ + col];
        }
#pragma unroll
        for (int j = 0; j < 4; ++j) {
            y = fmaf(aa[j], y, vv[j]);
            float r  = rr[j];
            float sr = r / (1.f + __expf(-r));
            float gv = sr * y;
            g_gbuf[(size_t)(b * TT + sm + j) * DD + col] = gv;
            s1 += gv;
            s2 = fmaf(gv, gv, s2);
        }
    }

    __shared__ float rs1[64], rs2[64];
    rs1[k] = s1; rs2[k] = s2;
    __syncthreads();
    for (int off = 32; off > 0; off >>= 1) {
        if (k < off) { rs1[k] += rs1[k + off]; rs2[k] += rs2[k + off]; }
        __syncthreads();
    }
    if (k == 0) g_psum[bh * NCH + c] = make_float2(rs1[0], rs2[0]);
}

// ---------------- GroupNorm statistics (deterministic combine) ----------------
__global__ void stats_kernel() {
    int gi = threadIdx.x;
    if (gi >= BB * HH) return;
    float s1 = 0.f, s2 = 0.f;
    for (int c = 0; c < NCH; ++c) {
        float2 p = g_psum[gi * NCH + c];
        s1 += p.x; s2 += p.y;
    }
    const float inv = 1.f / (float)(KH * TT);
    float mean = s1 * inv;
    float var  = s2 * inv - mean * mean;
    g_stats[gi] = make_float2(mean, rsqrtf(var + 1e-5f));
}

// ---------------- normalize + affine + fp16 convert (x4) ----------------
__global__ void normcvt_kernel(const float* __restrict__ gn_w, const float* __restrict__ gn_b) {
    int i4 = blockIdx.x * blockDim.x + threadIdx.x;
    if (i4 >= MMR * DD / 4) return;
    int idx = i4 * 4;
    int d  = idx & (DD - 1);
    int bt = idx >> 10;
    int b  = bt >> 11;
    int h  = d >> 6;
    float2 st = g_stats[b * HH + h];
    float4 gv = *(const float4*)(g_gbuf + idx);
    float4 w4 = *(const float4*)(gn_w + d);
    float4 b4 = *(const float4*)(gn_b + d);
    __half2* ph = (__half2*)(g_gh + idx);
    ph[0] = __halves2half2(__float2half_rn(fmaf((gv.x - st.x) * st.y, w4.x, b4.x)),
                           __float2half_rn(fmaf((gv.y - st.x) * st.y, w4.y, b4.y)));
    ph[1] = __halves2half2(__float2half_rn(fmaf((gv.z - st.x) * st.y, w4.z, b4.z)),
                           __float2half_rn(fmaf((gv.w - st.x) * st.y, w4.w, b4.w)));
}

// ---------------- launch ----------------
extern "C" void kernel_launch(void* const* d_in, const int* in_sizes, int n_in,
                              void* d_out, int out_size) {
    const float* x      = (const float*)d_in[0];
    const float* W_in   = (const float*)d_in[1];
    const float* conv_w = (const float*)d_in[2];
    const float* conv_b = (const float*)d_in[3];
    const float* dp     = (const float*)d_in[4];
    const float* gn_w   = (const float*)d_in[5];
    const float* gn_b   = (const float*)d_in[6];
    const float* W_out  = (const float*)d_in[7];
    float* out = (float*)d_out;
    (void)in_sizes; (void)n_in; (void)out_size;

    void *pxh, *pwih, *pwoh, *pproj, *pgh;
    cudaGetSymbolAddress(&pxh,  g_xh);
    cudaGetSymbolAddress(&pwih, g_wih);
    cudaGetSymbolAddress(&pwoh, g_woh);
    cudaGetSymbolAddress(&pproj, g_proj);
    cudaGetSymbolAddress(&pgh,  g_gh);

    cudaFuncSetAttribute(gemm1p_kernel,
                         cudaFuncAttributeMaxDynamicSharedMemorySize, GSMEM);

    const int TPB = 256;
    cvt_kernel<<<(MMR*DD/4 + TPB-1)/TPB, TPB>>>((const float4*)x,     (__half2*)pxh,  MMR*DD/4);
    cvt_kernel<<<(NPJ*DD/4 + TPB-1)/TPB, TPB>>>((const float4*)W_in,  (__half2*)pwih, NPJ*DD/4);
    cvt_kernel<<<(DD*DD/4  + TPB-1)/TPB, TPB>>>((const float4*)W_out, (__half2*)pwoh, DD*DD/4);

    // GEMM1: proj = x @ W_in^T (single-pass fp16, fp32 accum)
    dim3 gg1((NPJ + BN - 1)/BN, MMR/BM);
    gemm1p_kernel<<<gg1, 256, GSMEM>>>((__half*)pxh, (__half*)pwih,
                                       (float*)pproj, MMR, NPJ, DD);

    gate_kernel <<<(MMR*DD/4 + TPB-1)/TPB, TPB>>>(conv_w, conv_b);
    decay_kernel<<<(BB*TT*HH + TPB-1)/TPB, TPB>>>(dp);
    scan_kernel <<<BB*HH*NCH, 64>>>();
    stats_kernel<<<1, 32>>>();
    normcvt_kernel<<<(MMR*DD/4 + TPB-1)/TPB, TPB>>>(gn_w, gn_b);

    // GEMM2: out = g_norm @ W_out^T
    dim3 gg2(DD/BN, MMR/BM);
    gemm1p_kernel<<<gg2, 256, GSMEM>>>((__half*)pgh, (__half*)pwoh,
                                       out, MMR, DD, DD);
}